// round 17
// baseline (speedup 1.0000x reference)
#include <cuda_runtime.h>
#include <math.h>
#include <float.h>

// ---------------------------------------------------------------------------
// EceLabelShift: equal-mass-bin ECE with label-shift weighting.
// R16: conf split into target/source kernels; source pass overlapped (2nd
//      stream, event fork/join) with the L2-resident quantile chain;
//      k_final folded into k_diff (last-block pattern); float4 element loops.
// ---------------------------------------------------------------------------

#define NC      100
#define NBINS   15
#define HSIZE   (1 << 18)            // conf in (0,1] -> bits>>12 < 0x40000
#define CHUNK   1024
#define NCHUNK  (HSIZE / CHUNK)      // 256
#define NRANK   32                   // 16 edges x (i, i+1) rank pairs
#define NMAX    500000

struct ZeroBlock {
    unsigned hist[HSIZE];
    unsigned subhist[NRANK * 4096];
    double   wnum[NBINS];
    double   total;
    unsigned cnt[NBINS];
    unsigned done;
};
__device__ ZeroBlock gz;

__device__ float    g_conf_t[NMAX];
__device__ float2   g_cs[NMAX];        // (conf_s, wper)
__device__ unsigned g_csum[NCHUNK];
__device__ int      g_rankBin[NRANK];
__device__ unsigned g_rankBase[NRANK];
__device__ float    g_srt[NRANK];

// rank (0-indexed order statistic) needed for edge pair t: (i, i+1), clamped.
__device__ __forceinline__ long long rank_for(int t, int nt) {
    int k = t >> 1;
    double xq = (double)k * (double)nt / 15.0;
    long long i = (long long)floor(xq);
    if (i > (long long)nt - 1) i = (long long)nt - 1;
    long long r = i + (t & 1);
    if (r > (long long)nt - 1) r = (long long)nt - 1;
    return r;
}

// Edge k (k in [0,16)) from the 32 order statistics in g_srt.
__device__ __forceinline__ float edge_for(int k, int nt) {
    if (k == 0)  return g_srt[0];
    if (k == 15) return g_srt[31];
    double xq = (double)k * (double)nt / 15.0;
    long long i = (long long)floor(xq);
    double frac = xq - (double)i;
    double a = g_srt[2 * k], b2 = g_srt[2 * k + 1];
    return (float)(a + frac * (b2 - a));
}

// Block-wide (1024 thr = 32 warps) inclusive scan of one unsigned per thread.
__device__ __forceinline__ unsigned blockScanIncl(unsigned v, unsigned* sh) {
    int tid = threadIdx.x, lane = tid & 31, w = tid >> 5;
    unsigned sc = v;
#pragma unroll
    for (int o = 1; o < 32; o <<= 1) {
        unsigned u = __shfl_up_sync(0xffffffffu, sc, o);
        if (lane >= o) sc += u;
    }
    if (lane == 31) sh[w] = sc;
    __syncthreads();
    if (w == 0) {
        unsigned t = sh[lane];
#pragma unroll
        for (int o = 1; o < 32; o <<= 1) {
            unsigned u = __shfl_up_sync(0xffffffffu, t, o);
            if (lane >= o) t += u;
        }
        sh[lane] = t;
    }
    __syncthreads();
    unsigned off = w ? sh[w - 1] : 0u;
    return sc + off;
}

// 4-step branchless bin search over 16 shared edges; caller checks range.
__device__ __forceinline__ int bin_of(float c, const float* se) {
    int b = 0;
    if (c > se[8])     b = 8;
    if (c > se[b + 4]) b += 4;
    if (c > se[b + 2]) b += 2;
    if (c > se[b + 1]) b += 1;
    return b;
}

// ---------------------------------------------------------------------------
// Target conf pass: 4 rows per warp, 8 lanes per row. conf + bit histogram.
// ---------------------------------------------------------------------------
__global__ void __launch_bounds__(256) k_conf_t(const float* __restrict__ lg, int n) {
    const int tid = threadIdx.x, lane = tid & 31, wid = tid >> 5;
    const int sub = lane & 7;
    const int g   = lane >> 3;
    int r = (blockIdx.x * (blockDim.x >> 5) + wid) * 4 + g;
    bool valid = r < n;

    const float4 neg = make_float4(-FLT_MAX, -FLT_MAX, -FLT_MAX, -FLT_MAX);
    float4 v0 = neg, v1 = neg, v2 = neg, v3 = neg;
    if (valid) {
        const float4* p = (const float4*)(lg + (size_t)r * NC);
        v0 = p[sub]; v1 = p[sub + 8]; v2 = p[sub + 16];
        if (sub == 0) v3 = p[24];
    }

    float m = fmaxf(fmaxf(fmaxf(v0.x, v0.y), fmaxf(v0.z, v0.w)),
              fmaxf(fmaxf(fmaxf(v1.x, v1.y), fmaxf(v1.z, v1.w)),
              fmaxf(fmaxf(fmaxf(v2.x, v2.y), fmaxf(v2.z, v2.w)),
                    fmaxf(fmaxf(v3.x, v3.y), fmaxf(v3.z, v3.w)))));
#pragma unroll
    for (int o = 4; o; o >>= 1) m = fmaxf(m, __shfl_xor_sync(0xffffffffu, m, o));

    float s = 0.0f;
    if (valid) {
        s  = __expf(v0.x - m) + __expf(v0.y - m) + __expf(v0.z - m) + __expf(v0.w - m);
        s += __expf(v1.x - m) + __expf(v1.y - m) + __expf(v1.z - m) + __expf(v1.w - m);
        s += __expf(v2.x - m) + __expf(v2.y - m) + __expf(v2.z - m) + __expf(v2.w - m);
        if (sub == 0)
            s += __expf(v3.x - m) + __expf(v3.y - m) + __expf(v3.z - m) + __expf(v3.w - m);
    }
#pragma unroll
    for (int o = 4; o; o >>= 1) s += __shfl_xor_sync(0xffffffffu, s, o);

    if (valid && sub == 0) {
        float c = 1.0f / s;
        g_conf_t[r] = c;
        atomicAdd(&gz.hist[__float_as_uint(c) >> 12], 1u);
    }
}

// ---------------------------------------------------------------------------
// Source conf pass: conf + first-occurrence argmax + w_per, packed float2.
// ---------------------------------------------------------------------------
__global__ void __launch_bounds__(256) k_conf_s(
    const float* __restrict__ lg, const void* __restrict__ labels,
    const float* __restrict__ wt, int n) {
    __shared__ int s_lab64;
    const int tid = threadIdx.x, lane = tid & 31, wid = tid >> 5;

    if (tid < 32) {   // int64 labels => odd 32-bit words of first 64 entries 0
        const unsigned* lb = (const unsigned*)labels;
        unsigned v = lb[2 * lane + 1] | lb[2 * lane + 65];
        unsigned mask = __ballot_sync(0xffffffffu, v != 0u);
        if (lane == 0) s_lab64 = (mask == 0u) ? 1 : 0;
    }
    __syncthreads();
    const int lab64 = s_lab64;

    const int sub = lane & 7;
    const int g   = lane >> 3;
    int r = (blockIdx.x * (blockDim.x >> 5) + wid) * 4 + g;
    bool valid = r < n;

    const float4 neg = make_float4(-FLT_MAX, -FLT_MAX, -FLT_MAX, -FLT_MAX);
    float4 v0 = neg, v1 = neg, v2 = neg, v3 = neg;
    if (valid) {
        const float4* p = (const float4*)(lg + (size_t)r * NC);
        v0 = p[sub]; v1 = p[sub + 8]; v2 = p[sub + 16];
        if (sub == 0) v3 = p[24];
    }

    float m = fmaxf(fmaxf(fmaxf(v0.x, v0.y), fmaxf(v0.z, v0.w)),
              fmaxf(fmaxf(fmaxf(v1.x, v1.y), fmaxf(v1.z, v1.w)),
              fmaxf(fmaxf(fmaxf(v2.x, v2.y), fmaxf(v2.z, v2.w)),
                    fmaxf(fmaxf(v3.x, v3.y), fmaxf(v3.z, v3.w)))));
#pragma unroll
    for (int o = 4; o; o >>= 1) m = fmaxf(m, __shfl_xor_sync(0xffffffffu, m, o));

    float s = 0.0f;
    if (valid) {
        s  = __expf(v0.x - m) + __expf(v0.y - m) + __expf(v0.z - m) + __expf(v0.w - m);
        s += __expf(v1.x - m) + __expf(v1.y - m) + __expf(v1.z - m) + __expf(v1.w - m);
        s += __expf(v2.x - m) + __expf(v2.y - m) + __expf(v2.z - m) + __expf(v2.w - m);
        if (sub == 0)
            s += __expf(v3.x - m) + __expf(v3.y - m) + __expf(v3.z - m) + __expf(v3.w - m);
    }
#pragma unroll
    for (int o = 4; o; o >>= 1) s += __shfl_xor_sync(0xffffffffu, s, o);

    int loc = 1 << 30;
    if (valid) {
        if (sub == 0) {
            if (v3.w == m) loc = 99;
            if (v3.z == m) loc = 98;
            if (v3.y == m) loc = 97;
            if (v3.x == m) loc = 96;
        }
        int b2 = 64 + 4 * sub;
        if (v2.w == m) loc = b2 + 3;
        if (v2.z == m) loc = b2 + 2;
        if (v2.y == m) loc = b2 + 1;
        if (v2.x == m) loc = b2;
        int b1 = 32 + 4 * sub;
        if (v1.w == m) loc = b1 + 3;
        if (v1.z == m) loc = b1 + 2;
        if (v1.y == m) loc = b1 + 1;
        if (v1.x == m) loc = b1;
        int b0 = 4 * sub;
        if (v0.w == m) loc = b0 + 3;
        if (v0.z == m) loc = b0 + 2;
        if (v0.y == m) loc = b0 + 1;
        if (v0.x == m) loc = b0;
    }
#pragma unroll
    for (int o = 4; o; o >>= 1) loc = min(loc, __shfl_xor_sync(0xffffffffu, loc, o));
    if (valid && sub == 0) {
        long long lab = lab64 ? ((const long long*)labels)[r]
                              : (long long)((const int*)labels)[r];
        float w = (loc == (int)lab) ? wt[lab] : 0.0f;
        g_cs[r] = make_float2(1.0f / s, w);
    }
}

// Per-chunk sums of the coarse histogram (grid = NCHUNK blocks).
__global__ void k_csum() {
    int c = blockIdx.x, tid = threadIdx.x;   // 256 threads
    unsigned s = 0;
#pragma unroll
    for (int j = 0; j < CHUNK / 256; j++) s += gz.hist[c * CHUNK + j * 256 + tid];
#pragma unroll
    for (int o = 16; o; o >>= 1) s += __shfl_xor_sync(0xffffffffu, s, o);
    __shared__ unsigned ws[8];
    if ((tid & 31) == 0) ws[tid >> 5] = s;
    __syncthreads();
    if (tid < 8) {
        unsigned v = ws[tid];
#pragma unroll
        for (int o = 4; o; o >>= 1) v += __shfl_xor_sync(0xffu, v, o);
        if (tid == 0) g_csum[c] = v;
    }
}

// One block per rank: prefix over chunk sums, locate chunk, block-scan chunk.
__global__ void k_rank(int nt) {
    __shared__ unsigned cpref[NCHUNK + 1];
    __shared__ unsigned sh[32];
    __shared__ int cIdx;
    __shared__ int firstIdx;
    int tid = threadIdx.x, b = blockIdx.x;
    if (tid == 0) firstIdx = 1 << 30;
    if (tid < 32) {
        unsigned s[8]; unsigned run = 0;
#pragma unroll
        for (int j = 0; j < 8; j++) { unsigned h = g_csum[tid * 8 + j]; s[j] = run; run += h; }
        unsigned sc = run;
#pragma unroll
        for (int o = 1; o < 32; o <<= 1) {
            unsigned u = __shfl_up_sync(0xffffffffu, sc, o);
            if (tid >= o) sc += u;
        }
        unsigned excl = sc - run;
#pragma unroll
        for (int j = 0; j < 8; j++) cpref[tid * 8 + j] = excl + s[j];
        if (tid == 31) cpref[NCHUNK] = excl + run;
    }
    __syncthreads();
    unsigned r = (unsigned)rank_for(b, nt);
    if (tid < NCHUNK && cpref[tid] <= r && r < cpref[tid + 1]) cIdx = tid;
    __syncthreads();
    int c = cIdx;
    unsigned h = gz.hist[c * CHUNK + tid];
    unsigned incl = blockScanIncl(h, sh);
    unsigned cum0 = cpref[c];
    if (cum0 + incl > r) atomicMin(&firstIdx, tid);
    __syncthreads();
    if (tid == firstIdx) {
        g_rankBin[b]  = c * CHUNK + tid;
        g_rankBase[b] = cum0 + incl - h;
    }
}

// Sub-histogram for UNIQUE rank bins (g_rankBin is non-decreasing):
// float4 loads; binary search the deduped list; <=1 atomic per element.
__global__ void k_refine(int nt) {
    __shared__ int ub[NRANK];
    __shared__ int s_nu;
    int tid = threadIdx.x;
    if (tid == 0) {
        int nu = 0, prev = -1;
#pragma unroll
        for (int t = 0; t < NRANK; t++) {
            int b = g_rankBin[t];
            if (b != prev) { ub[nu++] = b; prev = b; }
        }
        s_nu = nu;
    }
    __syncthreads();
    const int nu = s_nu;
    const int bmin = ub[0], bmax = ub[nu - 1];
    int stride = gridDim.x * blockDim.x;
    int gtid = blockIdx.x * blockDim.x + tid;
    int n4 = nt >> 2;
    const float4* ct4 = (const float4*)g_conf_t;
    for (int i = gtid; i < n4; i += stride) {
        float4 c4 = ct4[i];
#pragma unroll
        for (int e = 0; e < 4; e++) {
            float cv = (e == 0) ? c4.x : (e == 1) ? c4.y : (e == 2) ? c4.z : c4.w;
            unsigned key = __float_as_uint(cv);
            int bbin = (int)(key >> 12);
            if (bbin < bmin || bbin > bmax) continue;
            int lo = 0, hi = nu;
            while (lo < hi) { int mid = (lo + hi) >> 1; if (ub[mid] < bbin) lo = mid + 1; else hi = mid; }
            if (lo < nu && ub[lo] == bbin)
                atomicAdd(&gz.subhist[lo * 4096 + (key & 4095u)], 1u);
        }
    }
    for (int i = (n4 << 2) + gtid; i < nt; i += stride) {
        unsigned key = __float_as_uint(g_conf_t[i]);
        int bbin = (int)(key >> 12);
        if (bbin < bmin || bbin > bmax) continue;
        int lo = 0, hi = nu;
        while (lo < hi) { int mid = (lo + hi) >> 1; if (ub[mid] < bbin) lo = mid + 1; else hi = mid; }
        if (lo < nu && ub[lo] == bbin)
            atomicAdd(&gz.subhist[lo * 4096 + (key & 4095u)], 1u);
    }
}

// One block per rank: block scan of its (deduped) sub-hist -> exact float.
__global__ void k_select(int nt) {
    __shared__ unsigned sh[32];
    __shared__ int firstIdx;
    __shared__ int s_slot;
    int tid = threadIdx.x, b = blockIdx.x;
    if (tid == 0) {
        firstIdx = 1 << 30;
        int nu = 0, prev = -1, slot = 0;
#pragma unroll
        for (int t = 0; t < NRANK; t++) {
            int bb = g_rankBin[t];
            if (bb != prev) { prev = bb; nu++; }
            if (t == b) slot = nu - 1;
        }
        s_slot = slot;
    }
    __syncthreads();
    unsigned target = (unsigned)(rank_for(b, nt) - (long long)g_rankBase[b]);
    unsigned h[4]; unsigned tsum = 0;
    int base = s_slot * 4096 + tid * 4;
#pragma unroll
    for (int j = 0; j < 4; j++) { h[j] = gz.subhist[base + j]; tsum += h[j]; }
    unsigned incl = blockScanIncl(tsum, sh);
    unsigned cum  = incl - tsum;
    int found = -1;
#pragma unroll
    for (int j = 0; j < 4; j++) {
        if (found < 0 && cum + h[j] > target) found = tid * 4 + j;
        cum += h[j];
    }
    if (found >= 0) atomicMin(&firstIdx, found);
    __syncthreads();
    if (tid == 0)
        g_srt[b] = __uint_as_float(((unsigned)g_rankBin[b] << 12) | (unsigned)firstIdx);
}

// Bin accumulation: blocks [0,srcBlocks) -> weighted_num, rest -> count_t.
__global__ void k_binacc(int ns, int nt, int srcBlocks) {
    __shared__ float    se[16];
    __shared__ float    swn[NBINS];
    __shared__ unsigned sct[NBINS];
    int tid = threadIdx.x;
    if (tid < 16)    se[tid] = edge_for(tid, nt);
    if (tid < NBINS) { swn[tid] = 0.0f; sct[tid] = 0u; }
    __syncthreads();
    if ((int)blockIdx.x < srcBlocks) {
        int stride = srcBlocks * blockDim.x;
        for (int i = blockIdx.x * blockDim.x + tid; i < ns; i += stride) {
            float2 cw = g_cs[i];
            if (cw.y != 0.0f) {
                float c = cw.x;
                if (c > se[0] && c <= se[15])
                    atomicAdd(&swn[bin_of(c, se)], cw.y);
            }
        }
    } else {
        int nb = gridDim.x - srcBlocks;
        int stride = nb * blockDim.x;
        int gtid = ((int)blockIdx.x - srcBlocks) * blockDim.x + tid;
        int n4 = nt >> 2;
        const float4* ct4 = (const float4*)g_conf_t;
        for (int i = gtid; i < n4; i += stride) {
            float4 c4 = ct4[i];
#pragma unroll
            for (int e = 0; e < 4; e++) {
                float c = (e == 0) ? c4.x : (e == 1) ? c4.y : (e == 2) ? c4.z : c4.w;
                if (c > se[0] && c <= se[15])
                    atomicAdd(&sct[bin_of(c, se)], 1u);
            }
        }
        for (int i = (n4 << 2) + gtid; i < nt; i += stride) {
            float c = g_conf_t[i];
            if (c > se[0] && c <= se[15])
                atomicAdd(&sct[bin_of(c, se)], 1u);
        }
    }
    __syncthreads();
    if (tid < NBINS) {
        if (swn[tid] != 0.0f) atomicAdd(&gz.wnum[tid], (double)swn[tid]);
        if (sct[tid])         atomicAdd(&gz.cnt[tid], sct[tid]);
    }
}

// Sum of (conf_t - cond_expect[bin])^2; edges + ce in preamble; last block
// writes the final scalar (fold of old k_final).
__global__ void k_diff(int ns, int nt, float* __restrict__ out) {
    __shared__ float se[16];
    __shared__ float sce[NBINS];
    __shared__ unsigned char sok[NBINS];
    int tid = threadIdx.x;
    if (tid < 16) se[tid] = edge_for(tid, nt);
    if (tid < NBINS) {
        long long ct = (long long)gz.cnt[tid];
        long long d  = ct - 1; if (d < 1) d = 1;
        double normal = (double)(nt - 1) / (double)ns;
        sce[tid] = (float)(normal * gz.wnum[tid] / (double)d);
        sok[tid] = (ct > 1) ? 1 : 0;
    }
    __syncthreads();
    double local = 0.0;
    int stride = gridDim.x * blockDim.x;
    int gtid = blockIdx.x * blockDim.x + tid;
    int n4 = nt >> 2;
    const float4* ct4 = (const float4*)g_conf_t;
    for (int i = gtid; i < n4; i += stride) {
        float4 c4 = ct4[i];
#pragma unroll
        for (int e = 0; e < 4; e++) {
            float c = (e == 0) ? c4.x : (e == 1) ? c4.y : (e == 2) ? c4.z : c4.w;
            if (c > se[0] && c <= se[15]) {
                int b = bin_of(c, se);
                if (sok[b]) { float d = c - sce[b]; local += (double)d * (double)d; }
            }
        }
    }
    for (int i = (n4 << 2) + gtid; i < nt; i += stride) {
        float c = g_conf_t[i];
        if (c > se[0] && c <= se[15]) {
            int b = bin_of(c, se);
            if (sok[b]) { float d = c - sce[b]; local += (double)d * (double)d; }
        }
    }
#pragma unroll
    for (int o = 16; o; o >>= 1) local += __shfl_down_sync(0xffffffffu, local, o);
    __shared__ double warpsum[8];
    if ((tid & 31) == 0) warpsum[tid >> 5] = local;
    __syncthreads();
    if (tid < 8) {
        double v = warpsum[tid];
#pragma unroll
        for (int o = 4; o; o >>= 1) v += __shfl_down_sync(0xffu, v, o);
        if (tid == 0) {
            atomicAdd(&gz.total, v);
            __threadfence();
            unsigned d = atomicAdd(&gz.done, 1u);
            if (d == gridDim.x - 1) {
                double tot = atomicAdd(&gz.total, 0.0);   // atomic read-back
                out[0] = (float)(tot / (double)nt);
            }
        }
    }
}

extern "C" void kernel_launch(void* const* d_in, const int* in_sizes, int n_in,
                              void* d_out, int out_size) {
    const float* lg_s = (const float*)d_in[0];
    const void*  lab  = d_in[1];
    const float* lg_t = (const float*)d_in[2];
    const float* wt   = (const float*)d_in[3];
    int ns = in_sizes[0] / NC;
    int nt = in_sizes[2] / NC;

    void* zp = nullptr;
    cudaGetSymbolAddress(&zp, gz);
    cudaMemsetAsync(zp, 0, sizeof(ZeroBlock), 0);

    cudaStream_t s1;
    cudaStreamCreateWithFlags(&s1, cudaStreamNonBlocking);
    cudaEvent_t evT, evS;
    cudaEventCreateWithFlags(&evT, cudaEventDisableTiming);
    cudaEventCreateWithFlags(&evS, cudaEventDisableTiming);

    // Target stream first: quantile chain depends only on it.
    int blocks_t = (nt + 31) / 32;     // 4 rows/warp, 8 warps/block
    k_conf_t<<<blocks_t, 256>>>(lg_t, nt);
    cudaEventRecord(evT, 0);

    // Source pass on s1, overlapping the quantile chain below.
    cudaStreamWaitEvent(s1, evT, 0);
    int blocks_s = (ns + 31) / 32;
    k_conf_s<<<blocks_s, 256, 0, s1>>>(lg_s, lab, wt, ns);
    cudaEventRecord(evS, s1);

    k_csum<<<NCHUNK, 256>>>();
    k_rank<<<NRANK, 1024>>>(nt);
    k_refine<<<888, 256>>>(nt);
    k_select<<<NRANK, 1024>>>(nt);

    cudaStreamWaitEvent(0, evS, 0);    // join: binacc needs source conf too
    k_binacc<<<1184, 256>>>(ns, nt, 592);
    k_diff<<<888, 256>>>(ns, nt, (float*)d_out);

    cudaEventDestroy(evT);
    cudaEventDestroy(evS);
    cudaStreamDestroy(s1);
    (void)n_in; (void)out_size;
}